// round 4
// baseline (speedup 1.0000x reference)
#include <cuda_runtime.h>
#include <stdint.h>

#define BB      4
#define NN      16384
#define NPOINT  2048
#define CC      64
#define NSAMPLE 32
#define GRID    10
#define NCELLS  1024        // 10*10*10 = 1000, padded (pad cells scan to total)
#define R2      0.01f
#define R2PRUNE 0.01001f    // prune margin (conservative vs float rounding)
#define CAND_CAP 192
#define OUTC    (CC + 3)    // 67
#define PPT     16          // points per thread in build

#define TR_TILES    ((NN / 32) * (CC / 32) * BB)   // 4096 tiles
#define TR_BLOCKS   (TR_TILES / 4)                 // 1024 blocks @ 4 tiles
#define BQ_BLOCKS   ((BB * NPOINT) / 8)            // 1024 blocks, 8 warps each

// scratch (static device globals; no allocation at runtime)
__device__ int    g_starts[BB * NCELLS];           // exclusive scan; starts[c+1] = end of c
__device__ float4 g_pts  [BB * NN];                // cell-ordered {x,y,z,bitcast(pid)}
__device__ int    g_idx  [BB * NPOINT * NSAMPLE];
__device__ float  g_ft   [BB * NN * CC];           // features transposed [B][N][C]

// ---------------------------------------------------------------- fused: grid build (4 blocks) + transpose (1024 blocks)
__global__ void __launch_bounds__(1024) build_tr_kernel(
    const float* __restrict__ xyz, const float* __restrict__ feat)
{
    if (blockIdx.x >= BB) {
        // ---- transpose: 4 tiles [B,C,N] -> [B,N,C] per block
        __shared__ float tile[4][32][33];
        int sub  = threadIdx.x >> 8;                 // 0..3
        int t256 = threadIdx.x & 255;
        int tb   = (blockIdx.x - BB) * 4 + sub;      // 0..4095
        int b    = tb / ((NN / 32) * (CC / 32));
        int rem  = tb % ((NN / 32) * (CC / 32));
        int n0   = (rem % (NN / 32)) * 32;
        int c0   = (rem / (NN / 32)) * 32;
        int tx = t256 & 31, ty = t256 >> 5;          // ty 0..7
#pragma unroll
        for (int k = 0; k < 32; k += 8)
            tile[sub][ty + k][tx] = feat[((size_t)(b * CC + c0 + ty + k)) * NN + n0 + tx];
        __syncthreads();
#pragma unroll
        for (int k = 0; k < 32; k += 8)
            g_ft[((size_t)(b * NN + n0 + ty + k)) * CC + c0 + tx] = tile[sub][tx][ty + k];
        return;
    }

    // ---- grid build: histogram + scan + scatter, all in one block per batch
    __shared__ int cnts[NCELLS];
    __shared__ int starts_s[NCELLS];
    __shared__ int wsum[32];

    int b = blockIdx.x;
    int t = threadIdx.x;
    int lane = t & 31, wid = t >> 5;

    cnts[t] = 0;
    __syncthreads();

    int cr[PPT];   // (cell<<20)|rank
#pragma unroll
    for (int k = 0; k < PPT; k++) {
        int i = t + k * 1024;
        const float* p = xyz + ((size_t)(b * NN + i)) * 3;
        float x = p[0], y = p[1], z = p[2];
        int cx = (int)(x * 10.0f); cx = cx < 0 ? 0 : (cx > GRID - 1 ? GRID - 1 : cx);
        int cy = (int)(y * 10.0f); cy = cy < 0 ? 0 : (cy > GRID - 1 ? GRID - 1 : cy);
        int cz = (int)(z * 10.0f); cz = cz < 0 ? 0 : (cz > GRID - 1 ? GRID - 1 : cz);
        int cell = (cz * GRID + cy) * GRID + cx;
        int rank = atomicAdd(&cnts[cell], 1);
        cr[k] = (cell << 20) | rank;
    }
    __syncthreads();

    // block-wide exclusive scan of cnts (warp shuffle scan)
    int v = cnts[t];
    int incl = v;
#pragma unroll
    for (int o = 1; o < 32; o <<= 1) {
        int y = __shfl_up_sync(0xffffffffu, incl, o);
        if (lane >= o) incl += y;
    }
    if (lane == 31) wsum[wid] = incl;
    __syncthreads();
    if (wid == 0) {
        int w = wsum[lane];
        int wi = w;
#pragma unroll
        for (int o = 1; o < 32; o <<= 1) {
            int y = __shfl_up_sync(0xffffffffu, wi, o);
            if (lane >= o) wi += y;
        }
        wsum[lane] = wi - w;   // exclusive warp offsets
    }
    __syncthreads();
    int excl = incl - v + wsum[wid];
    starts_s[t] = excl;
    g_starts[b * NCELLS + t] = excl;
    __syncthreads();

    // scatter (atomic-free; reload xyz)
#pragma unroll
    for (int k = 0; k < PPT; k++) {
        int i = t + k * 1024;
        const float* p = xyz + ((size_t)(b * NN + i)) * 3;
        int cell = cr[k] >> 20;
        int rank = cr[k] & 0xfffff;
        int slot = starts_s[cell] + rank;
        g_pts[b * NN + slot] = make_float4(p[0], p[1], p[2], __int_as_float(i));
    }
}

// ---------------------------------------------------------------- register bitonic helpers
__device__ __forceinline__ int bsort32(int v, int lane) {
#pragma unroll
    for (int k = 2; k <= 32; k <<= 1) {
#pragma unroll
        for (int j = k >> 1; j > 0; j >>= 1) {
            int p = __shfl_xor_sync(0xffffffffu, v, j);
            bool keep_min = ((lane & j) == 0) == ((lane & k) == 0);
            v = keep_min ? min(v, p) : max(v, p);
        }
    }
    return v;   // ascending across lanes
}

// ---------------------------------------------------------------- ball query (warp per query)
__global__ void __launch_bounds__(256) bq_kernel(const float* __restrict__ new_xyz)
{
    __shared__ int buf_s[8][CAND_CAP];
    int warp = threadIdx.x >> 5;
    int lane = threadIdx.x & 31;
    int qid  = blockIdx.x * 8 + warp;
    int b = qid / NPOINT;

    float qx = new_xyz[qid * 3 + 0];
    float qy = new_xyz[qid * 3 + 1];
    float qz = new_xyz[qid * 3 + 2];
    int cx = (int)(qx * 10.0f); cx = cx < 0 ? 0 : (cx > GRID - 1 ? GRID - 1 : cx);
    int cy = (int)(qy * 10.0f); cy = cy < 0 ? 0 : (cy > GRID - 1 ? GRID - 1 : cy);
    int cz = (int)(qz * 10.0f); cz = cz < 0 ? 0 : (cz > GRID - 1 ? GRID - 1 : cz);

    int* buf = buf_s[warp];
    int cnt = 0;

    int z0 = cz > 0 ? cz - 1 : 0, z1 = cz < GRID - 1 ? cz + 1 : GRID - 1;
    int y0 = cy > 0 ? cy - 1 : 0, y1 = cy < GRID - 1 ? cy + 1 : GRID - 1;
    int x0 = cx > 0 ? cx - 1 : 0, x1 = cx < GRID - 1 ? cx + 1 : GRID - 1;

    const float4* pts = g_pts + b * NN;
    const int* starts = g_starts + b * NCELLS;

    for (int zc = z0; zc <= z1; zc++) {
        float dz = (zc < cz) ? (qz - (zc + 1) * 0.1f) : ((zc > cz) ? (zc * 0.1f - qz) : 0.0f);
        float dz2 = dz * dz;
        for (int yc = y0; yc <= y1; yc++) {
            float dy = (yc < cy) ? (qy - (yc + 1) * 0.1f) : ((yc > cy) ? (yc * 0.1f - qy) : 0.0f);
            if (dz2 + dy * dy >= R2PRUNE) continue;   // span cannot contain hits
            int base = (zc * GRID + yc) * GRID;
            int s0 = starts[base + x0];
            int e  = starts[base + x1 + 1];   // x-cells contiguous
            int len = e - s0;
            for (int j0 = 0; j0 < len; j0 += 32) {
                int j = j0 + lane;
                bool valid = false;
                int pid = 0;
                if (j < len) {
                    float4 p = pts[s0 + j];
                    float ddx = qx - p.x;
                    float ddy = qy - p.y;
                    float ddz = qz - p.z;
                    valid = (ddx * ddx + ddy * ddy + ddz * ddz) < R2;
                    pid = __float_as_int(p.w);
                }
                unsigned m = __ballot_sync(0xffffffffu, valid);
                int off = __popc(m & ((1u << lane) - 1));
                if (valid && (cnt + off) < CAND_CAP) buf[cnt + off] = pid;
                cnt += __popc(m);
                if (cnt > CAND_CAP) cnt = CAND_CAP;
            }
        }
    }
    __syncwarp();

    // ---- top-32 smallest (ascending) via register bitonic sort+merge
    int res = (lane < cnt) ? buf[lane] : 0x7fffffff;
    res = bsort32(res, lane);
    int nchunks = (cnt + 31) >> 5;
    for (int c = 1; c < nchunks; c++) {
        int idx = c * 32 + lane;
        int v = (idx < cnt) ? buf[idx] : 0x7fffffff;
        v = bsort32(v, lane);
        int vr = __shfl_sync(0xffffffffu, v, 31 - lane);   // reverse
        res = min(res, vr);                                 // bitonic, smallest 32
#pragma unroll
        for (int j = 16; j > 0; j >>= 1) {                  // clean
            int p = __shfl_xor_sync(0xffffffffu, res, j);
            res = ((lane & j) == 0) ? min(res, p) : max(res, p);
        }
    }
    int first = __shfl_sync(0xffffffffu, res, 0);
    int outv = (cnt == 0) ? 0 : ((lane < cnt) ? res : first);
    g_idx[qid * NSAMPLE + lane] = outv;
}

// ---------------------------------------------------------------- grouping (block per query)
__global__ void __launch_bounds__(128) group_kernel(
    const float* __restrict__ xyz, const float* __restrict__ new_xyz,
    float* __restrict__ out)
{
    __shared__ int   sidx[NSAMPLE];
    __shared__ float T[NSAMPLE][OUTC];   // stride 67: conflict-free transposed reads

    int qid = blockIdx.x;
    int b = qid / NPOINT;
    int p = qid % NPOINT;
    int t = threadIdx.x;

    if (t < 32) sidx[t] = g_idx[qid * NSAMPLE + t];
    __syncthreads();

    // gather feature rows (256B each, contiguous) into registers
    int s4 = t >> 2, q = t & 3;
    const float4* row = (const float4*)(g_ft + ((size_t)(b * NN + sidx[s4])) * CC) + q * 4;
    float4 v0 = row[0];
    float4 v1 = row[1];
    float4 v2 = row[2];
    float4 v3 = row[3];

    // centered xyz channels
    float xv = 0.0f; int cxi = 0, sxi = 0;
    if (t < 96) {
        cxi = t >> 5; sxi = t & 31;
        xv = xyz[((size_t)(b * NN + sidx[sxi])) * 3 + cxi]
           - new_xyz[((size_t)(b * NPOINT + p)) * 3 + cxi];
    }

    // stage features into smem
    float* dst = &T[s4][q * 16];
    dst[0]  = v0.x; dst[1]  = v0.y; dst[2]  = v0.z; dst[3]  = v0.w;
    dst[4]  = v1.x; dst[5]  = v1.y; dst[6]  = v1.z; dst[7]  = v1.w;
    dst[8]  = v2.x; dst[9]  = v2.y; dst[10] = v2.z; dst[11] = v2.w;
    dst[12] = v3.x; dst[13] = v3.y; dst[14] = v3.z; dst[15] = v3.w;
    __syncthreads();

    if (t < 96)
        out[(((size_t)b * OUTC + cxi) * NPOINT + p) * NSAMPLE + sxi] = xv;

    // feature output: float4 along sample dim, STG.128 coalesced
    float4* out4 = (float4*)(out + (((size_t)b * OUTC + 3) * NPOINT + p) * NSAMPLE);
#pragma unroll
    for (int k = 0; k < 4; k++) {
        int f  = t + 128 * k;
        int c  = f >> 3;
        int sq = f & 7;
        float4 w;
        w.x = T[4 * sq + 0][c];
        w.y = T[4 * sq + 1][c];
        w.z = T[4 * sq + 2][c];
        w.w = T[4 * sq + 3][c];
        out4[(size_t)c * (NPOINT * NSAMPLE / 4) + sq] = w;
    }
}

// ---------------------------------------------------------------- launch
extern "C" void kernel_launch(void* const* d_in, const int* in_sizes, int n_in,
                              void* d_out, int out_size)
{
    const float* xyz     = (const float*)d_in[0];
    const float* new_xyz = (const float*)d_in[1];
    const float* feat    = (const float*)d_in[2];
    float* out = (float*)d_out;

    build_tr_kernel<<<BB + TR_BLOCKS, 1024>>>(xyz, feat);
    bq_kernel<<<BQ_BLOCKS, 256>>>(new_xyz);
    group_kernel<<<BB * NPOINT, 128>>>(xyz, new_xyz, out);
}

// round 5
// speedup vs baseline: 1.1038x; 1.1038x over previous
#include <cuda_runtime.h>
#include <stdint.h>

#define BB      4
#define NN      16384
#define NPOINT  2048
#define CC      64
#define NSAMPLE 32
#define GRID    10
#define NCELLS  1024        // 10*10*10 = 1000, padded (pad cells scan to total)
#define R2      0.01f
#define R2PRUNE 0.01001f
#define CAND_CAP 192
#define OUTC    (CC + 3)    // 67

#define HIST_BLOCKS 64                              // 64 x 256 = 16384 threads (4 pts each)
#define TR_TILES    ((NN / 32) * (CC / 32) * BB)    // 4096 tiles @ 256 threads
#define SC_BLOCKS   64                              // 16 per batch, 1024 pts each

// scratch (static device globals; no allocation at runtime)
__device__ int    g_counts[BB * NCELLS];
__device__ int    g_starts[BB * NCELLS];           // exclusive scan; starts[c+1] = end of c
__device__ int    g_cellrank[BB * NN];             // (cell<<20)|rank
__device__ float4 g_pts  [BB * NN];                // cell-ordered {x,y,z,bitcast(pid)}
__device__ float  g_ft   [BB * NN * CC];           // features transposed [B][N][C]

// ---------------------------------------------------------------- K1: hist (64 blocks) + transpose (4096 blocks)
__global__ void __launch_bounds__(256) hist_tr_kernel(
    const float* __restrict__ xyz, const float* __restrict__ feat)
{
    if (blockIdx.x >= HIST_BLOCKS) {
        // ---- transpose tile: [B,C,N] -> [B,N,C]
        __shared__ float tile[32][33];
        int tb  = blockIdx.x - HIST_BLOCKS;
        int b   = tb / ((NN / 32) * (CC / 32));
        int rem = tb % ((NN / 32) * (CC / 32));
        int n0  = (rem % (NN / 32)) * 32;
        int c0  = (rem / (NN / 32)) * 32;
        int tx = threadIdx.x & 31, ty = threadIdx.x >> 5;   // ty 0..7
#pragma unroll
        for (int k = 0; k < 32; k += 8)
            tile[ty + k][tx] = feat[((size_t)(b * CC + c0 + ty + k)) * NN + n0 + tx];
        __syncthreads();
#pragma unroll
        for (int k = 0; k < 32; k += 8)
            g_ft[((size_t)(b * NN + n0 + ty + k)) * CC + c0 + tx] = tile[tx][ty + k];
        return;
    }

    // ---- histogram (+rank), 4 points per thread
    int t0 = blockIdx.x * 256 + threadIdx.x;
#pragma unroll
    for (int k = 0; k < 4; k++) {
        int i = t0 + k * (HIST_BLOCKS * 256);
        float x = xyz[i * 3 + 0];
        float y = xyz[i * 3 + 1];
        float z = xyz[i * 3 + 2];
        int cx = (int)(x * 10.0f); cx = cx < 0 ? 0 : (cx > GRID - 1 ? GRID - 1 : cx);
        int cy = (int)(y * 10.0f); cy = cy < 0 ? 0 : (cy > GRID - 1 ? GRID - 1 : cy);
        int cz = (int)(z * 10.0f); cz = cz < 0 ? 0 : (cz > GRID - 1 ? GRID - 1 : cz);
        int cell = (cz * GRID + cy) * GRID + cx;
        int b = i / NN;
        int rank = atomicAdd(&g_counts[b * NCELLS + cell], 1);
        g_cellrank[i] = (cell << 20) | rank;
    }
}

// ---------------------------------------------------------------- K2: scan (redundant per block) + scatter
__global__ void __launch_bounds__(256) scan_scatter_kernel(const float* __restrict__ xyz)
{
    __shared__ int starts_s[NCELLS];
    __shared__ int wsum[8];

    int bb = blockIdx.x;          // 0..63
    int b  = bb >> 4;             // batch
    int t  = threadIdx.x;
    int lane = t & 31, wid = t >> 5;

    // block scan of this batch's 1024 cell counts (4 per thread)
    int base = t * 4;
    const int* cnt = g_counts + b * NCELLS;
    int a0 = cnt[base + 0], a1 = cnt[base + 1], a2 = cnt[base + 2], a3 = cnt[base + 3];
    int s = a0 + a1 + a2 + a3;
    int incl = s;
#pragma unroll
    for (int o = 1; o < 32; o <<= 1) {
        int y = __shfl_up_sync(0xffffffffu, incl, o);
        if (lane >= o) incl += y;
    }
    if (lane == 31) wsum[wid] = incl;
    __syncthreads();
    if (wid == 0 && lane < 8) {
        int w = wsum[lane];
        int wi = w;
#pragma unroll
        for (int o = 1; o < 8; o <<= 1) {
            int y = __shfl_up_sync(0x000000ffu, wi, o);
            if (lane >= o) wi += y;
        }
        wsum[lane] = wi - w;   // exclusive warp offsets
    }
    __syncthreads();
    int excl = incl - s + wsum[wid];
    starts_s[base + 0] = excl;
    starts_s[base + 1] = excl + a0;
    starts_s[base + 2] = excl + a0 + a1;
    starts_s[base + 3] = excl + a0 + a1 + a2;
    __syncthreads();

    // one block per batch publishes starts for bq
    if ((bb & 15) == 0) {
#pragma unroll
        for (int k = 0; k < 4; k++)
            g_starts[b * NCELLS + base + k] = starts_s[base + k];
    }

    // scatter this block's 1024-point chunk
    int chunk = (bb & 15) * 1024;
#pragma unroll
    for (int k = 0; k < 4; k++) {
        int i = chunk + t + k * 256;           // local point index in batch
        int gi = b * NN + i;
        int cr = g_cellrank[gi];
        int cell = cr >> 20;
        int rank = cr & 0xfffff;
        int slot = starts_s[cell] + rank;
        const float* p = xyz + (size_t)gi * 3;
        g_pts[b * NN + slot] = make_float4(p[0], p[1], p[2], __int_as_float(i));
    }
}

// ---------------------------------------------------------------- register bitonic helpers
__device__ __forceinline__ int bsort32(int v, int lane) {
#pragma unroll
    for (int k = 2; k <= 32; k <<= 1) {
#pragma unroll
        for (int j = k >> 1; j > 0; j >>= 1) {
            int p = __shfl_xor_sync(0xffffffffu, v, j);
            bool keep_min = ((lane & j) == 0) == ((lane & k) == 0);
            v = keep_min ? min(v, p) : max(v, p);
        }
    }
    return v;   // ascending across lanes
}

// ---------------------------------------------------------------- K3: fused ball query + group (block per query)
__global__ void __launch_bounds__(128) bq_group_kernel(
    const float* __restrict__ xyz, const float* __restrict__ new_xyz,
    float* __restrict__ out)
{
    __shared__ int   buf[CAND_CAP];
    __shared__ int   sidx[NSAMPLE];
    __shared__ float T[NSAMPLE][OUTC];   // stride 67: conflict-free transposed reads

    int qid = blockIdx.x;
    int b = qid / NPOINT;
    int p = qid % NPOINT;
    int t = threadIdx.x;
    int lane = t & 31;

    // ---- warp 0: ball query
    if (t < 32) {
        float qx = new_xyz[qid * 3 + 0];
        float qy = new_xyz[qid * 3 + 1];
        float qz = new_xyz[qid * 3 + 2];
        int cx = (int)(qx * 10.0f); cx = cx < 0 ? 0 : (cx > GRID - 1 ? GRID - 1 : cx);
        int cy = (int)(qy * 10.0f); cy = cy < 0 ? 0 : (cy > GRID - 1 ? GRID - 1 : cy);
        int cz = (int)(qz * 10.0f); cz = cz < 0 ? 0 : (cz > GRID - 1 ? GRID - 1 : cz);

        int cnt = 0;
        int z0 = cz > 0 ? cz - 1 : 0, z1 = cz < GRID - 1 ? cz + 1 : GRID - 1;
        int y0 = cy > 0 ? cy - 1 : 0, y1 = cy < GRID - 1 ? cy + 1 : GRID - 1;
        int x0 = cx > 0 ? cx - 1 : 0, x1 = cx < GRID - 1 ? cx + 1 : GRID - 1;

        const float4* pts = g_pts + b * NN;
        const int* starts = g_starts + b * NCELLS;

        for (int zc = z0; zc <= z1; zc++) {
            float dz = (zc < cz) ? (qz - (zc + 1) * 0.1f) : ((zc > cz) ? (zc * 0.1f - qz) : 0.0f);
            float dz2 = dz * dz;
            for (int yc = y0; yc <= y1; yc++) {
                float dy = (yc < cy) ? (qy - (yc + 1) * 0.1f) : ((yc > cy) ? (yc * 0.1f - qy) : 0.0f);
                if (dz2 + dy * dy >= R2PRUNE) continue;
                int bse = (zc * GRID + yc) * GRID;
                int s0 = starts[bse + x0];
                int e  = starts[bse + x1 + 1];
                int len = e - s0;
                for (int j0 = 0; j0 < len; j0 += 32) {
                    int j = j0 + lane;
                    bool valid = false;
                    int pid = 0;
                    if (j < len) {
                        float4 pt = pts[s0 + j];
                        float ddx = qx - pt.x;
                        float ddy = qy - pt.y;
                        float ddz = qz - pt.z;
                        valid = (ddx * ddx + ddy * ddy + ddz * ddz) < R2;
                        pid = __float_as_int(pt.w);
                    }
                    unsigned m = __ballot_sync(0xffffffffu, valid);
                    int off = __popc(m & ((1u << lane) - 1));
                    if (valid && (cnt + off) < CAND_CAP) buf[cnt + off] = pid;
                    cnt += __popc(m);
                    if (cnt > CAND_CAP) cnt = CAND_CAP;
                }
            }
        }
        __syncwarp();

        // top-32 smallest via register bitonic sort+merge
        int res = (lane < cnt) ? buf[lane] : 0x7fffffff;
        res = bsort32(res, lane);
        int nchunks = (cnt + 31) >> 5;
        for (int c = 1; c < nchunks; c++) {
            int idx = c * 32 + lane;
            int v = (idx < cnt) ? buf[idx] : 0x7fffffff;
            v = bsort32(v, lane);
            int vr = __shfl_sync(0xffffffffu, v, 31 - lane);
            res = min(res, vr);
#pragma unroll
            for (int j = 16; j > 0; j >>= 1) {
                int pp = __shfl_xor_sync(0xffffffffu, res, j);
                res = ((lane & j) == 0) ? min(res, pp) : max(res, pp);
            }
        }
        int first = __shfl_sync(0xffffffffu, res, 0);
        sidx[lane] = (cnt == 0) ? 0 : ((lane < cnt) ? res : first);
    }
    __syncthreads();

    // ---- group
    int s4 = t >> 2, q = t & 3;
    const float4* row = (const float4*)(g_ft + ((size_t)(b * NN + sidx[s4])) * CC) + q * 4;
    float4 v0 = row[0];
    float4 v1 = row[1];
    float4 v2 = row[2];
    float4 v3 = row[3];

    // centered xyz channels
    float xv = 0.0f; int cxi = 0, sxi = 0;
    if (t < 96) {
        cxi = t >> 5; sxi = t & 31;
        xv = xyz[((size_t)(b * NN + sidx[sxi])) * 3 + cxi]
           - new_xyz[((size_t)(b * NPOINT + p)) * 3 + cxi];
    }

    float* dst = &T[s4][q * 16];
    dst[0]  = v0.x; dst[1]  = v0.y; dst[2]  = v0.z; dst[3]  = v0.w;
    dst[4]  = v1.x; dst[5]  = v1.y; dst[6]  = v1.z; dst[7]  = v1.w;
    dst[8]  = v2.x; dst[9]  = v2.y; dst[10] = v2.z; dst[11] = v2.w;
    dst[12] = v3.x; dst[13] = v3.y; dst[14] = v3.z; dst[15] = v3.w;
    __syncthreads();

    if (t < 96)
        out[(((size_t)b * OUTC + cxi) * NPOINT + p) * NSAMPLE + sxi] = xv;

    // feature output: float4 along sample dim, STG.128 coalesced
    float4* out4 = (float4*)(out + (((size_t)b * OUTC + 3) * NPOINT + p) * NSAMPLE);
#pragma unroll
    for (int k = 0; k < 4; k++) {
        int f  = t + 128 * k;
        int c  = f >> 3;
        int sq = f & 7;
        float4 w;
        w.x = T[4 * sq + 0][c];
        w.y = T[4 * sq + 1][c];
        w.z = T[4 * sq + 2][c];
        w.w = T[4 * sq + 3][c];
        out4[(size_t)c * (NPOINT * NSAMPLE / 4) + sq] = w;
    }
}

// ---------------------------------------------------------------- launch
extern "C" void kernel_launch(void* const* d_in, const int* in_sizes, int n_in,
                              void* d_out, int out_size)
{
    const float* xyz     = (const float*)d_in[0];
    const float* new_xyz = (const float*)d_in[1];
    const float* feat    = (const float*)d_in[2];
    float* out = (float*)d_out;

    void* counts_ptr = nullptr;
    cudaGetSymbolAddress(&counts_ptr, g_counts);
    cudaMemsetAsync(counts_ptr, 0, BB * NCELLS * sizeof(int), 0);

    hist_tr_kernel<<<HIST_BLOCKS + TR_TILES, 256>>>(xyz, feat);
    scan_scatter_kernel<<<SC_BLOCKS, 256>>>(xyz);
    bq_group_kernel<<<BB * NPOINT, 128>>>(xyz, new_xyz, out);
}

// round 6
// speedup vs baseline: 1.1459x; 1.0381x over previous
#include <cuda_runtime.h>
#include <stdint.h>

#define BB      4
#define NN      16384
#define NPOINT  2048
#define CC      64
#define NSAMPLE 32
#define GRID    10
#define NCELLS  1024        // 10*10*10 = 1000, padded (pad cells scan to total)
#define R2      0.01f
#define R2PRUNE 0.01001f
#define CAND_CAP 192
#define OUTC    (CC + 3)    // 67

#define HIST_BLOCKS 64                              // 64 x 256 = 16384 threads (4 pts each)
#define TR_TILES    ((NN / 32) * (CC / 32) * BB)    // 4096 tiles @ 256 threads
#define SC_BLOCKS   64                              // 16 per batch, 1024 pts each
#define BQ_BLOCKS   ((BB * NPOINT) / 8)             // 1024 blocks, 8 warps each

// scratch (static device globals; no allocation at runtime)
__device__ int    g_counts[BB * NCELLS];
__device__ int    g_starts[BB * NCELLS];           // exclusive scan; starts[c+1] = end of c
__device__ int    g_cellrank[BB * NN];             // (cell<<20)|rank
__device__ float4 g_pts  [BB * NN];                // cell-ordered {x,y,z,bitcast(pid)}
__device__ int    g_idx  [BB * NPOINT * NSAMPLE];
__device__ float  g_ft   [BB * NN * CC];           // features transposed [B][N][C]

// ---------------------------------------------------------------- K1: hist (64 blocks) + transpose (4096 blocks)
__global__ void __launch_bounds__(256) hist_tr_kernel(
    const float* __restrict__ xyz, const float* __restrict__ feat)
{
    if (blockIdx.x >= HIST_BLOCKS) {
        // ---- transpose tile: [B,C,N] -> [B,N,C]
        __shared__ float tile[32][33];
        int tb  = blockIdx.x - HIST_BLOCKS;
        int b   = tb / ((NN / 32) * (CC / 32));
        int rem = tb % ((NN / 32) * (CC / 32));
        int n0  = (rem % (NN / 32)) * 32;
        int c0  = (rem / (NN / 32)) * 32;
        int tx = threadIdx.x & 31, ty = threadIdx.x >> 5;   // ty 0..7
#pragma unroll
        for (int k = 0; k < 32; k += 8)
            tile[ty + k][tx] = feat[((size_t)(b * CC + c0 + ty + k)) * NN + n0 + tx];
        __syncthreads();
#pragma unroll
        for (int k = 0; k < 32; k += 8)
            g_ft[((size_t)(b * NN + n0 + ty + k)) * CC + c0 + tx] = tile[tx][ty + k];
        return;
    }

    // ---- histogram (+rank), 4 points per thread
    int t0 = blockIdx.x * 256 + threadIdx.x;
#pragma unroll
    for (int k = 0; k < 4; k++) {
        int i = t0 + k * (HIST_BLOCKS * 256);
        float x = xyz[i * 3 + 0];
        float y = xyz[i * 3 + 1];
        float z = xyz[i * 3 + 2];
        int cx = (int)(x * 10.0f); cx = cx < 0 ? 0 : (cx > GRID - 1 ? GRID - 1 : cx);
        int cy = (int)(y * 10.0f); cy = cy < 0 ? 0 : (cy > GRID - 1 ? GRID - 1 : cy);
        int cz = (int)(z * 10.0f); cz = cz < 0 ? 0 : (cz > GRID - 1 ? GRID - 1 : cz);
        int cell = (cz * GRID + cy) * GRID + cx;
        int b = i / NN;
        int rank = atomicAdd(&g_counts[b * NCELLS + cell], 1);
        g_cellrank[i] = (cell << 20) | rank;
    }
}

// ---------------------------------------------------------------- K2: scan (redundant per block) + scatter
__global__ void __launch_bounds__(256) scan_scatter_kernel(const float* __restrict__ xyz)
{
    __shared__ int starts_s[NCELLS];
    __shared__ int wsum[8];

    int bb = blockIdx.x;          // 0..63
    int b  = bb >> 4;             // batch
    int t  = threadIdx.x;
    int lane = t & 31, wid = t >> 5;

    // block scan of this batch's 1024 cell counts (4 per thread)
    int base = t * 4;
    const int* cnt = g_counts + b * NCELLS;
    int a0 = cnt[base + 0], a1 = cnt[base + 1], a2 = cnt[base + 2], a3 = cnt[base + 3];
    int s = a0 + a1 + a2 + a3;
    int incl = s;
#pragma unroll
    for (int o = 1; o < 32; o <<= 1) {
        int y = __shfl_up_sync(0xffffffffu, incl, o);
        if (lane >= o) incl += y;
    }
    if (lane == 31) wsum[wid] = incl;
    __syncthreads();
    if (wid == 0 && lane < 8) {
        int w = wsum[lane];
        int wi = w;
#pragma unroll
        for (int o = 1; o < 8; o <<= 1) {
            int y = __shfl_up_sync(0x000000ffu, wi, o);
            if (lane >= o) wi += y;
        }
        wsum[lane] = wi - w;   // exclusive warp offsets
    }
    __syncthreads();
    int excl = incl - s + wsum[wid];
    starts_s[base + 0] = excl;
    starts_s[base + 1] = excl + a0;
    starts_s[base + 2] = excl + a0 + a1;
    starts_s[base + 3] = excl + a0 + a1 + a2;
    __syncthreads();

    // one block per batch publishes starts for bq
    if ((bb & 15) == 0) {
#pragma unroll
        for (int k = 0; k < 4; k++)
            g_starts[b * NCELLS + base + k] = starts_s[base + k];
    }

    // scatter this block's 1024-point chunk
    int chunk = (bb & 15) * 1024;
#pragma unroll
    for (int k = 0; k < 4; k++) {
        int i = chunk + t + k * 256;           // local point index in batch
        int gi = b * NN + i;
        int cr = g_cellrank[gi];
        int cell = cr >> 20;
        int rank = cr & 0xfffff;
        int slot = starts_s[cell] + rank;
        const float* p = xyz + (size_t)gi * 3;
        g_pts[b * NN + slot] = make_float4(p[0], p[1], p[2], __int_as_float(i));
    }
}

// ---------------------------------------------------------------- register bitonic helpers
__device__ __forceinline__ int bsort32(int v, int lane) {
#pragma unroll
    for (int k = 2; k <= 32; k <<= 1) {
#pragma unroll
        for (int j = k >> 1; j > 0; j >>= 1) {
            int p = __shfl_xor_sync(0xffffffffu, v, j);
            bool keep_min = ((lane & j) == 0) == ((lane & k) == 0);
            v = keep_min ? min(v, p) : max(v, p);
        }
    }
    return v;   // ascending across lanes
}

// ---------------------------------------------------------------- K3: ball query (warp per query, 8 warps/block)
__global__ void __launch_bounds__(256) bq_kernel(const float* __restrict__ new_xyz)
{
    __shared__ int buf_s[8][CAND_CAP];
    int warp = threadIdx.x >> 5;
    int lane = threadIdx.x & 31;
    int qid  = blockIdx.x * 8 + warp;
    int b = qid / NPOINT;

    float qx = new_xyz[qid * 3 + 0];
    float qy = new_xyz[qid * 3 + 1];
    float qz = new_xyz[qid * 3 + 2];
    int cx = (int)(qx * 10.0f); cx = cx < 0 ? 0 : (cx > GRID - 1 ? GRID - 1 : cx);
    int cy = (int)(qy * 10.0f); cy = cy < 0 ? 0 : (cy > GRID - 1 ? GRID - 1 : cy);
    int cz = (int)(qz * 10.0f); cz = cz < 0 ? 0 : (cz > GRID - 1 ? GRID - 1 : cz);

    int* buf = buf_s[warp];
    int cnt = 0;

    int z0 = cz > 0 ? cz - 1 : 0, z1 = cz < GRID - 1 ? cz + 1 : GRID - 1;
    int y0 = cy > 0 ? cy - 1 : 0, y1 = cy < GRID - 1 ? cy + 1 : GRID - 1;
    int x0 = cx > 0 ? cx - 1 : 0, x1 = cx < GRID - 1 ? cx + 1 : GRID - 1;

    const float4* pts = g_pts + b * NN;
    const int* starts = g_starts + b * NCELLS;

    for (int zc = z0; zc <= z1; zc++) {
        float dz = (zc < cz) ? (qz - (zc + 1) * 0.1f) : ((zc > cz) ? (zc * 0.1f - qz) : 0.0f);
        float dz2 = dz * dz;
        for (int yc = y0; yc <= y1; yc++) {
            float dy = (yc < cy) ? (qy - (yc + 1) * 0.1f) : ((yc > cy) ? (yc * 0.1f - qy) : 0.0f);
            if (dz2 + dy * dy >= R2PRUNE) continue;   // span cannot contain hits
            int bse = (zc * GRID + yc) * GRID;
            int s0 = starts[bse + x0];
            int e  = starts[bse + x1 + 1];   // x-cells contiguous
            int len = e - s0;
            for (int j0 = 0; j0 < len; j0 += 32) {
                int j = j0 + lane;
                bool valid = false;
                int pid = 0;
                if (j < len) {
                    float4 p = pts[s0 + j];
                    float ddx = qx - p.x;
                    float ddy = qy - p.y;
                    float ddz = qz - p.z;
                    valid = (ddx * ddx + ddy * ddy + ddz * ddz) < R2;
                    pid = __float_as_int(p.w);
                }
                unsigned m = __ballot_sync(0xffffffffu, valid);
                int off = __popc(m & ((1u << lane) - 1));
                if (valid && (cnt + off) < CAND_CAP) buf[cnt + off] = pid;
                cnt += __popc(m);
                if (cnt > CAND_CAP) cnt = CAND_CAP;
            }
        }
    }
    __syncwarp();

    // ---- top-32 smallest (ascending) via register bitonic sort+merge
    int res = (lane < cnt) ? buf[lane] : 0x7fffffff;
    res = bsort32(res, lane);
    int nchunks = (cnt + 31) >> 5;
    for (int c = 1; c < nchunks; c++) {
        int idx = c * 32 + lane;
        int v = (idx < cnt) ? buf[idx] : 0x7fffffff;
        v = bsort32(v, lane);
        int vr = __shfl_sync(0xffffffffu, v, 31 - lane);   // reverse
        res = min(res, vr);                                 // bitonic, smallest 32
#pragma unroll
        for (int j = 16; j > 0; j >>= 1) {                  // clean
            int p = __shfl_xor_sync(0xffffffffu, res, j);
            res = ((lane & j) == 0) ? min(res, p) : max(res, p);
        }
    }
    int first = __shfl_sync(0xffffffffu, res, 0);
    int outv = (cnt == 0) ? 0 : ((lane < cnt) ? res : first);
    g_idx[qid * NSAMPLE + lane] = outv;
}

// ---------------------------------------------------------------- K4: grouping (block per query)
__global__ void __launch_bounds__(128) group_kernel(
    const float* __restrict__ xyz, const float* __restrict__ new_xyz,
    float* __restrict__ out)
{
    __shared__ int   sidx[NSAMPLE];
    __shared__ float T[NSAMPLE][OUTC];   // stride 67: conflict-free transposed reads

    int qid = blockIdx.x;
    int b = qid / NPOINT;
    int p = qid % NPOINT;
    int t = threadIdx.x;

    if (t < 32) sidx[t] = g_idx[qid * NSAMPLE + t];
    __syncthreads();

    // gather feature rows (256B each, contiguous) into registers
    int s4 = t >> 2, q = t & 3;
    const float4* row = (const float4*)(g_ft + ((size_t)(b * NN + sidx[s4])) * CC) + q * 4;
    float4 v0 = row[0];
    float4 v1 = row[1];
    float4 v2 = row[2];
    float4 v3 = row[3];

    // centered xyz channels
    float xv = 0.0f; int cxi = 0, sxi = 0;
    if (t < 96) {
        cxi = t >> 5; sxi = t & 31;
        xv = xyz[((size_t)(b * NN + sidx[sxi])) * 3 + cxi]
           - new_xyz[((size_t)(b * NPOINT + p)) * 3 + cxi];
    }

    // stage features into smem
    float* dst = &T[s4][q * 16];
    dst[0]  = v0.x; dst[1]  = v0.y; dst[2]  = v0.z; dst[3]  = v0.w;
    dst[4]  = v1.x; dst[5]  = v1.y; dst[6]  = v1.z; dst[7]  = v1.w;
    dst[8]  = v2.x; dst[9]  = v2.y; dst[10] = v2.z; dst[11] = v2.w;
    dst[12] = v3.x; dst[13] = v3.y; dst[14] = v3.z; dst[15] = v3.w;
    __syncthreads();

    if (t < 96)
        out[(((size_t)b * OUTC + cxi) * NPOINT + p) * NSAMPLE + sxi] = xv;

    // feature output: float4 along sample dim, STG.128 coalesced
    float4* out4 = (float4*)(out + (((size_t)b * OUTC + 3) * NPOINT + p) * NSAMPLE);
#pragma unroll
    for (int k = 0; k < 4; k++) {
        int f  = t + 128 * k;
        int c  = f >> 3;
        int sq = f & 7;
        float4 w;
        w.x = T[4 * sq + 0][c];
        w.y = T[4 * sq + 1][c];
        w.z = T[4 * sq + 2][c];
        w.w = T[4 * sq + 3][c];
        out4[(size_t)c * (NPOINT * NSAMPLE / 4) + sq] = w;
    }
}

// ---------------------------------------------------------------- launch
extern "C" void kernel_launch(void* const* d_in, const int* in_sizes, int n_in,
                              void* d_out, int out_size)
{
    const float* xyz     = (const float*)d_in[0];
    const float* new_xyz = (const float*)d_in[1];
    const float* feat    = (const float*)d_in[2];
    float* out = (float*)d_out;

    void* counts_ptr = nullptr;
    cudaGetSymbolAddress(&counts_ptr, g_counts);
    cudaMemsetAsync(counts_ptr, 0, BB * NCELLS * sizeof(int), 0);

    hist_tr_kernel<<<HIST_BLOCKS + TR_TILES, 256>>>(xyz, feat);
    scan_scatter_kernel<<<SC_BLOCKS, 256>>>(xyz);
    bq_kernel<<<BQ_BLOCKS, 256>>>(new_xyz);
    group_kernel<<<BB * NPOINT, 128>>>(xyz, new_xyz, out);
}

// round 7
// speedup vs baseline: 1.2341x; 1.0770x over previous
#include <cuda_runtime.h>
#include <stdint.h>

#define BB      4
#define NN      16384
#define NPOINT  2048
#define CC      64
#define NSAMPLE 32
#define GRID    10
#define NCELLS  1024        // 10*10*10 = 1000, padded (pad cells scan to total)
#define R2      0.01f
#define R2PRUNE 0.01001f
#define CAND_CAP 192
#define OUTC    (CC + 3)    // 67

#define HIST_BLOCKS 64                              // 64 x 256 = 16384 threads (4 pts each)
#define TR_TILES    ((NN / 32) * (CC / 32) * BB)    // 4096 tiles @ 256 threads
#define SC_BLOCKS   64                              // 16 per batch, 1024 pts each
#define BQ_BLOCKS   ((BB * NPOINT) / 8)             // 1024 blocks, 8 warps each

// scratch (static device globals; zero-initialized at module load).
// g_counts is re-zeroed by bq_kernel each run so replays start clean.
__device__ int    g_counts[BB * NCELLS];
__device__ int    g_starts[BB * NCELLS];           // exclusive scan; starts[c+1] = end of c
__device__ int    g_cellrank[BB * NN];             // (cell<<20)|rank
__device__ float4 g_pts  [BB * NN];                // cell-ordered {x,y,z,bitcast(pid)}
__device__ int    g_idx  [BB * NPOINT * NSAMPLE];
__device__ float  g_ft   [BB * NN * CC];           // features transposed [B][N][C]

// ---------------------------------------------------------------- K1: hist (64 blocks) + transpose (4096 blocks)
__global__ void __launch_bounds__(256) hist_tr_kernel(
    const float* __restrict__ xyz, const float* __restrict__ feat)
{
    if (blockIdx.x >= HIST_BLOCKS) {
        // ---- transpose tile: [B,C,N] -> [B,N,C], float4 both directions
        __shared__ float tile[32][33];
        int tb  = blockIdx.x - HIST_BLOCKS;
        int b   = tb / ((NN / 32) * (CC / 32));
        int rem = tb % ((NN / 32) * (CC / 32));
        int n0  = (rem % (NN / 32)) * 32;
        int c0  = (rem / (NN / 32)) * 32;
        int t   = threadIdx.x;

        int c  = t >> 3;          // 0..31 (channel within tile)
        int nq = t & 7;           // 0..7  (n quad)
        float4 v = *(const float4*)(feat + ((size_t)(b * CC + c0 + c)) * NN + n0 + 4 * nq);
        tile[4 * nq + 0][c] = v.x;   // banks (4nq+k+c)%32: conflict-free
        tile[4 * nq + 1][c] = v.y;
        tile[4 * nq + 2][c] = v.z;
        tile[4 * nq + 3][c] = v.w;
        __syncthreads();

        int n  = t >> 3;          // 0..31
        int cq = t & 7;           // 0..7
        float4 w = make_float4(tile[n][4 * cq + 0], tile[n][4 * cq + 1],
                               tile[n][4 * cq + 2], tile[n][4 * cq + 3]);
        *(float4*)(g_ft + ((size_t)(b * NN + n0 + n)) * CC + c0 + 4 * cq) = w;
        return;
    }

    // ---- histogram (+rank), 4 points per thread
    int t0 = blockIdx.x * 256 + threadIdx.x;
#pragma unroll
    for (int k = 0; k < 4; k++) {
        int i = t0 + k * (HIST_BLOCKS * 256);
        float x = xyz[i * 3 + 0];
        float y = xyz[i * 3 + 1];
        float z = xyz[i * 3 + 2];
        int cx = (int)(x * 10.0f); cx = cx < 0 ? 0 : (cx > GRID - 1 ? GRID - 1 : cx);
        int cy = (int)(y * 10.0f); cy = cy < 0 ? 0 : (cy > GRID - 1 ? GRID - 1 : cy);
        int cz = (int)(z * 10.0f); cz = cz < 0 ? 0 : (cz > GRID - 1 ? GRID - 1 : cz);
        int cell = (cz * GRID + cy) * GRID + cx;
        int b = i / NN;
        int rank = atomicAdd(&g_counts[b * NCELLS + cell], 1);
        g_cellrank[i] = (cell << 20) | rank;
    }
}

// ---------------------------------------------------------------- K2: scan (redundant per block) + scatter
__global__ void __launch_bounds__(256) scan_scatter_kernel(const float* __restrict__ xyz)
{
    __shared__ int starts_s[NCELLS];
    __shared__ int wsum[8];

    int bb = blockIdx.x;          // 0..63
    int b  = bb >> 4;             // batch
    int t  = threadIdx.x;
    int lane = t & 31, wid = t >> 5;

    // block scan of this batch's 1024 cell counts (4 per thread)
    int base = t * 4;
    const int* cnt = g_counts + b * NCELLS;
    int a0 = cnt[base + 0], a1 = cnt[base + 1], a2 = cnt[base + 2], a3 = cnt[base + 3];
    int s = a0 + a1 + a2 + a3;
    int incl = s;
#pragma unroll
    for (int o = 1; o < 32; o <<= 1) {
        int y = __shfl_up_sync(0xffffffffu, incl, o);
        if (lane >= o) incl += y;
    }
    if (lane == 31) wsum[wid] = incl;
    __syncthreads();
    if (wid == 0 && lane < 8) {
        int w = wsum[lane];
        int wi = w;
#pragma unroll
        for (int o = 1; o < 8; o <<= 1) {
            int y = __shfl_up_sync(0x000000ffu, wi, o);
            if (lane >= o) wi += y;
        }
        wsum[lane] = wi - w;   // exclusive warp offsets
    }
    __syncthreads();
    int excl = incl - s + wsum[wid];
    starts_s[base + 0] = excl;
    starts_s[base + 1] = excl + a0;
    starts_s[base + 2] = excl + a0 + a1;
    starts_s[base + 3] = excl + a0 + a1 + a2;
    __syncthreads();

    // one block per batch publishes starts for bq
    if ((bb & 15) == 0) {
#pragma unroll
        for (int k = 0; k < 4; k++)
            g_starts[b * NCELLS + base + k] = starts_s[base + k];
    }

    // scatter this block's 1024-point chunk
    int chunk = (bb & 15) * 1024;
#pragma unroll
    for (int k = 0; k < 4; k++) {
        int i = chunk + t + k * 256;           // local point index in batch
        int gi = b * NN + i;
        int cr = g_cellrank[gi];
        int cell = cr >> 20;
        int rank = cr & 0xfffff;
        int slot = starts_s[cell] + rank;
        const float* p = xyz + (size_t)gi * 3;
        g_pts[b * NN + slot] = make_float4(p[0], p[1], p[2], __int_as_float(i));
    }
}

// ---------------------------------------------------------------- register bitonic helpers
__device__ __forceinline__ int bsort32(int v, int lane) {
#pragma unroll
    for (int k = 2; k <= 32; k <<= 1) {
#pragma unroll
        for (int j = k >> 1; j > 0; j >>= 1) {
            int p = __shfl_xor_sync(0xffffffffu, v, j);
            bool keep_min = ((lane & j) == 0) == ((lane & k) == 0);
            v = keep_min ? min(v, p) : max(v, p);
        }
    }
    return v;   // ascending across lanes
}

// ---------------------------------------------------------------- K3: ball query (warp per query, 8 warps/block)
__global__ void __launch_bounds__(256) bq_kernel(const float* __restrict__ new_xyz)
{
    // re-zero g_counts for the next run (scan_scatter has finished reading it)
    if (blockIdx.x < (BB * NCELLS) / 256)
        g_counts[blockIdx.x * 256 + threadIdx.x] = 0;

    __shared__ int buf_s[8][CAND_CAP];
    int warp = threadIdx.x >> 5;
    int lane = threadIdx.x & 31;
    int qid  = blockIdx.x * 8 + warp;
    int b = qid / NPOINT;

    float qx = new_xyz[qid * 3 + 0];
    float qy = new_xyz[qid * 3 + 1];
    float qz = new_xyz[qid * 3 + 2];
    int cx = (int)(qx * 10.0f); cx = cx < 0 ? 0 : (cx > GRID - 1 ? GRID - 1 : cx);
    int cy = (int)(qy * 10.0f); cy = cy < 0 ? 0 : (cy > GRID - 1 ? GRID - 1 : cy);
    int cz = (int)(qz * 10.0f); cz = cz < 0 ? 0 : (cz > GRID - 1 ? GRID - 1 : cz);

    int* buf = buf_s[warp];
    int cnt = 0;

    int z0 = cz > 0 ? cz - 1 : 0, z1 = cz < GRID - 1 ? cz + 1 : GRID - 1;
    int y0 = cy > 0 ? cy - 1 : 0, y1 = cy < GRID - 1 ? cy + 1 : GRID - 1;
    int x0 = cx > 0 ? cx - 1 : 0, x1 = cx < GRID - 1 ? cx + 1 : GRID - 1;

    const float4* pts = g_pts + b * NN;
    const int* starts = g_starts + b * NCELLS;

    for (int zc = z0; zc <= z1; zc++) {
        float dz = (zc < cz) ? (qz - (zc + 1) * 0.1f) : ((zc > cz) ? (zc * 0.1f - qz) : 0.0f);
        float dz2 = dz * dz;
        for (int yc = y0; yc <= y1; yc++) {
            float dy = (yc < cy) ? (qy - (yc + 1) * 0.1f) : ((yc > cy) ? (yc * 0.1f - qy) : 0.0f);
            if (dz2 + dy * dy >= R2PRUNE) continue;   // span cannot contain hits
            int bse = (zc * GRID + yc) * GRID;
            int s0 = starts[bse + x0];
            int e  = starts[bse + x1 + 1];   // x-cells contiguous
            int len = e - s0;
            for (int j0 = 0; j0 < len; j0 += 32) {
                int j = j0 + lane;
                bool valid = false;
                int pid = 0;
                if (j < len) {
                    float4 p = pts[s0 + j];
                    float ddx = qx - p.x;
                    float ddy = qy - p.y;
                    float ddz = qz - p.z;
                    valid = (ddx * ddx + ddy * ddy + ddz * ddz) < R2;
                    pid = __float_as_int(p.w);
                }
                unsigned m = __ballot_sync(0xffffffffu, valid);
                int off = __popc(m & ((1u << lane) - 1));
                if (valid && (cnt + off) < CAND_CAP) buf[cnt + off] = pid;
                cnt += __popc(m);
                if (cnt > CAND_CAP) cnt = CAND_CAP;
            }
        }
    }
    __syncwarp();

    // ---- top-32 smallest (ascending) via register bitonic sort+merge
    int res = (lane < cnt) ? buf[lane] : 0x7fffffff;
    res = bsort32(res, lane);
    int nchunks = (cnt + 31) >> 5;
    for (int c = 1; c < nchunks; c++) {
        int idx = c * 32 + lane;
        int v = (idx < cnt) ? buf[idx] : 0x7fffffff;
        v = bsort32(v, lane);
        int vr = __shfl_sync(0xffffffffu, v, 31 - lane);   // reverse
        res = min(res, vr);                                 // bitonic, smallest 32
#pragma unroll
        for (int j = 16; j > 0; j >>= 1) {                  // clean
            int p = __shfl_xor_sync(0xffffffffu, res, j);
            res = ((lane & j) == 0) ? min(res, p) : max(res, p);
        }
    }
    int first = __shfl_sync(0xffffffffu, res, 0);
    int outv = (cnt == 0) ? 0 : ((lane < cnt) ? res : first);
    g_idx[qid * NSAMPLE + lane] = outv;
}

// ---------------------------------------------------------------- K4: grouping (block per query), warp-coherent gather
__global__ void __launch_bounds__(128) group_kernel(
    const float* __restrict__ xyz, const float* __restrict__ new_xyz,
    float* __restrict__ out)
{
    __shared__ int   sidx[NSAMPLE];
    __shared__ __align__(16) float T[NSAMPLE][OUTC];   // stride 67

    int qid = blockIdx.x;
    int b = qid / NPOINT;
    int p = qid % NPOINT;
    int t = threadIdx.x;
    int lane = t & 31;
    int w = t >> 5;

    if (t < 32) sidx[t] = g_idx[qid * NSAMPLE + t];
    __syncthreads();

    // ---- gather: warp w loads samples w*8..w*8+7, one full row per warp (coalesced)
#pragma unroll
    for (int j = 0; j < 8; j++) {
        int s = w * 8 + j;                 // parity(s) == parity(j)
        int row = sidx[s];
        const float2* rp = (const float2*)(g_ft + ((size_t)(b * NN + row)) * CC);
        float2 v = rp[lane];               // 256B per row, 2 wavefronts
        if ((j & 1) == 0) {
            *(float2*)&T[s][2 * lane] = v; // 8B-aligned: s even => s*67 even
        } else {
            T[s][2 * lane + 0] = v.x;
            T[s][2 * lane + 1] = v.y;
        }
    }

    // ---- centered xyz channels
    float xv = 0.0f; int cxi = 0, sxi = 0;
    if (t < 96) {
        cxi = t >> 5; sxi = t & 31;
        xv = xyz[((size_t)(b * NN + sidx[sxi])) * 3 + cxi]
           - new_xyz[((size_t)(b * NPOINT + p)) * 3 + cxi];
    }
    __syncthreads();

    if (t < 96)
        out[(((size_t)b * OUTC + cxi) * NPOINT + p) * NSAMPLE + sxi] = xv;

    // ---- feature output: float4 along sample dim, STG.128 coalesced
    float4* out4 = (float4*)(out + (((size_t)b * OUTC + 3) * NPOINT + p) * NSAMPLE);
#pragma unroll
    for (int k = 0; k < 4; k++) {
        int f  = t + 128 * k;
        int c  = f >> 3;
        int sq = f & 7;
        float4 wv;
        wv.x = T[4 * sq + 0][c];
        wv.y = T[4 * sq + 1][c];
        wv.z = T[4 * sq + 2][c];
        wv.w = T[4 * sq + 3][c];
        out4[(size_t)c * (NPOINT * NSAMPLE / 4) + sq] = wv;
    }
}

// ---------------------------------------------------------------- launch
extern "C" void kernel_launch(void* const* d_in, const int* in_sizes, int n_in,
                              void* d_out, int out_size)
{
    const float* xyz     = (const float*)d_in[0];
    const float* new_xyz = (const float*)d_in[1];
    const float* feat    = (const float*)d_in[2];
    float* out = (float*)d_out;

    hist_tr_kernel<<<HIST_BLOCKS + TR_TILES, 256>>>(xyz, feat);
    scan_scatter_kernel<<<SC_BLOCKS, 256>>>(xyz);
    bq_kernel<<<BQ_BLOCKS, 256>>>(new_xyz);
    group_kernel<<<BB * NPOINT, 128>>>(xyz, new_xyz, out);
}

// round 8
// speedup vs baseline: 1.2861x; 1.0421x over previous
#include <cuda_runtime.h>
#include <stdint.h>

#define BB      4
#define NN      16384
#define NPOINT  2048
#define CC      64
#define NSAMPLE 32
#define GRID    10
#define NCELLS  1024        // 10*10*10 = 1000, padded (pad cells scan to total)
#define R2      0.01f
#define R2PRUNE 0.01001f
#define CAND_CAP 192
#define OUTC    (CC + 3)    // 67

#define HIST_BLOCKS 64                              // 64 x 256 = 16384 threads (4 pts each)
#define TR_TILES    ((NN / 32) * (CC / 32) * BB)    // 4096 tiles @ 256 threads
#define SC_BLOCKS   64                              // 16 per batch, 1024 pts each
#define BQ_BLOCKS   ((BB * NPOINT) / 8)             // 1024 blocks, 8 warps each

// scratch (static device globals; zero-initialized at module load).
// g_counts is re-zeroed inside bq blocks each run so replays start clean.
__device__ int    g_counts[BB * NCELLS];
__device__ int    g_starts[BB * NCELLS];           // exclusive scan; starts[c+1] = end of c
__device__ int    g_cellrank[BB * NN];             // (cell<<20)|rank
__device__ float4 g_pts  [BB * NN];                // cell-ordered {x,y,z,bitcast(pid)}
__device__ int    g_idx  [BB * NPOINT * NSAMPLE];
__device__ float  g_ft   [BB * NN * CC];           // features transposed [B][N][C]

// ---------------------------------------------------------------- K1: histogram (+rank)
__global__ void __launch_bounds__(256) hist_kernel(const float* __restrict__ xyz)
{
    int t0 = blockIdx.x * 256 + threadIdx.x;
#pragma unroll
    for (int k = 0; k < 4; k++) {
        int i = t0 + k * (HIST_BLOCKS * 256);
        float x = xyz[i * 3 + 0];
        float y = xyz[i * 3 + 1];
        float z = xyz[i * 3 + 2];
        int cx = (int)(x * 10.0f); cx = cx < 0 ? 0 : (cx > GRID - 1 ? GRID - 1 : cx);
        int cy = (int)(y * 10.0f); cy = cy < 0 ? 0 : (cy > GRID - 1 ? GRID - 1 : cy);
        int cz = (int)(z * 10.0f); cz = cz < 0 ? 0 : (cz > GRID - 1 ? GRID - 1 : cz);
        int cell = (cz * GRID + cy) * GRID + cx;
        int b = i / NN;
        int rank = atomicAdd(&g_counts[b * NCELLS + cell], 1);
        g_cellrank[i] = (cell << 20) | rank;
    }
}

// ---------------------------------------------------------------- K2: scan (redundant per block) + scatter
__global__ void __launch_bounds__(256) scan_scatter_kernel(const float* __restrict__ xyz)
{
    __shared__ int starts_s[NCELLS];
    __shared__ int wsum[8];

    int bb = blockIdx.x;          // 0..63
    int b  = bb >> 4;             // batch
    int t  = threadIdx.x;
    int lane = t & 31, wid = t >> 5;

    int base = t * 4;
    const int* cnt = g_counts + b * NCELLS;
    int a0 = cnt[base + 0], a1 = cnt[base + 1], a2 = cnt[base + 2], a3 = cnt[base + 3];
    int s = a0 + a1 + a2 + a3;
    int incl = s;
#pragma unroll
    for (int o = 1; o < 32; o <<= 1) {
        int y = __shfl_up_sync(0xffffffffu, incl, o);
        if (lane >= o) incl += y;
    }
    if (lane == 31) wsum[wid] = incl;
    __syncthreads();
    if (wid == 0 && lane < 8) {
        int w = wsum[lane];
        int wi = w;
#pragma unroll
        for (int o = 1; o < 8; o <<= 1) {
            int y = __shfl_up_sync(0x000000ffu, wi, o);
            if (lane >= o) wi += y;
        }
        wsum[lane] = wi - w;
    }
    __syncthreads();
    int excl = incl - s + wsum[wid];
    starts_s[base + 0] = excl;
    starts_s[base + 1] = excl + a0;
    starts_s[base + 2] = excl + a0 + a1;
    starts_s[base + 3] = excl + a0 + a1 + a2;
    __syncthreads();

    if ((bb & 15) == 0) {
#pragma unroll
        for (int k = 0; k < 4; k++)
            g_starts[b * NCELLS + base + k] = starts_s[base + k];
    }

    int chunk = (bb & 15) * 1024;
#pragma unroll
    for (int k = 0; k < 4; k++) {
        int i = chunk + t + k * 256;
        int gi = b * NN + i;
        int cr = g_cellrank[gi];
        int cell = cr >> 20;
        int rank = cr & 0xfffff;
        int slot = starts_s[cell] + rank;
        const float* p = xyz + (size_t)gi * 3;
        g_pts[b * NN + slot] = make_float4(p[0], p[1], p[2], __int_as_float(i));
    }
}

// ---------------------------------------------------------------- register bitonic helpers
__device__ __forceinline__ int bsort32(int v, int lane) {
#pragma unroll
    for (int k = 2; k <= 32; k <<= 1) {
#pragma unroll
        for (int j = k >> 1; j > 0; j >>= 1) {
            int p = __shfl_xor_sync(0xffffffffu, v, j);
            bool keep_min = ((lane & j) == 0) == ((lane & k) == 0);
            v = keep_min ? min(v, p) : max(v, p);
        }
    }
    return v;   // ascending across lanes
}

// ---------------------------------------------------------------- K3: ball query (warp/query) ∥ feature transpose
__global__ void __launch_bounds__(256) bq_tr_kernel(
    const float* __restrict__ new_xyz, const float* __restrict__ feat)
{
    if (blockIdx.x >= BQ_BLOCKS) {
        // ---- transpose tile: [B,C,N] -> [B,N,C], float4 both directions
        __shared__ float tile[32][33];
        int tb  = blockIdx.x - BQ_BLOCKS;
        int b   = tb / ((NN / 32) * (CC / 32));
        int rem = tb % ((NN / 32) * (CC / 32));
        int n0  = (rem % (NN / 32)) * 32;
        int c0  = (rem / (NN / 32)) * 32;
        int t   = threadIdx.x;

        int c  = t >> 3;          // 0..31
        int nq = t & 7;           // 0..7
        float4 v = *(const float4*)(feat + ((size_t)(b * CC + c0 + c)) * NN + n0 + 4 * nq);
        tile[4 * nq + 0][c] = v.x;
        tile[4 * nq + 1][c] = v.y;
        tile[4 * nq + 2][c] = v.z;
        tile[4 * nq + 3][c] = v.w;
        __syncthreads();

        int n  = t >> 3;
        int cq = t & 7;
        float4 w = make_float4(tile[n][4 * cq + 0], tile[n][4 * cq + 1],
                               tile[n][4 * cq + 2], tile[n][4 * cq + 3]);
        *(float4*)(g_ft + ((size_t)(b * NN + n0 + n)) * CC + c0 + 4 * cq) = w;
        return;
    }

    // re-zero g_counts for the next run (scan_scatter already consumed it)
    if (blockIdx.x < (BB * NCELLS) / 256)
        g_counts[blockIdx.x * 256 + threadIdx.x] = 0;

    __shared__ int buf_s[8][CAND_CAP];
    int warp = threadIdx.x >> 5;
    int lane = threadIdx.x & 31;
    int qid  = blockIdx.x * 8 + warp;
    int b = qid / NPOINT;

    float qx = new_xyz[qid * 3 + 0];
    float qy = new_xyz[qid * 3 + 1];
    float qz = new_xyz[qid * 3 + 2];
    int cx = (int)(qx * 10.0f); cx = cx < 0 ? 0 : (cx > GRID - 1 ? GRID - 1 : cx);
    int cy = (int)(qy * 10.0f); cy = cy < 0 ? 0 : (cy > GRID - 1 ? GRID - 1 : cy);
    int cz = (int)(qz * 10.0f); cz = cz < 0 ? 0 : (cz > GRID - 1 ? GRID - 1 : cz);

    int* buf = buf_s[warp];
    int cnt = 0;

    int z0 = cz > 0 ? cz - 1 : 0, z1 = cz < GRID - 1 ? cz + 1 : GRID - 1;
    int y0 = cy > 0 ? cy - 1 : 0, y1 = cy < GRID - 1 ? cy + 1 : GRID - 1;
    int x0 = cx > 0 ? cx - 1 : 0, x1 = cx < GRID - 1 ? cx + 1 : GRID - 1;

    const float4* pts = g_pts + b * NN;
    const int* starts = g_starts + b * NCELLS;

    for (int zc = z0; zc <= z1; zc++) {
        float dz = (zc < cz) ? (qz - (zc + 1) * 0.1f) : ((zc > cz) ? (zc * 0.1f - qz) : 0.0f);
        float dz2 = dz * dz;
        for (int yc = y0; yc <= y1; yc++) {
            float dy = (yc < cy) ? (qy - (yc + 1) * 0.1f) : ((yc > cy) ? (yc * 0.1f - qy) : 0.0f);
            if (dz2 + dy * dy >= R2PRUNE) continue;
            int bse = (zc * GRID + yc) * GRID;
            int s0 = starts[bse + x0];
            int e  = starts[bse + x1 + 1];
            int len = e - s0;
            for (int j0 = 0; j0 < len; j0 += 32) {
                int j = j0 + lane;
                bool valid = false;
                int pid = 0;
                if (j < len) {
                    float4 p = pts[s0 + j];
                    float ddx = qx - p.x;
                    float ddy = qy - p.y;
                    float ddz = qz - p.z;
                    valid = (ddx * ddx + ddy * ddy + ddz * ddz) < R2;
                    pid = __float_as_int(p.w);
                }
                unsigned m = __ballot_sync(0xffffffffu, valid);
                int off = __popc(m & ((1u << lane) - 1));
                if (valid && (cnt + off) < CAND_CAP) buf[cnt + off] = pid;
                cnt += __popc(m);
                if (cnt > CAND_CAP) cnt = CAND_CAP;
            }
        }
    }
    __syncwarp();

    int res = (lane < cnt) ? buf[lane] : 0x7fffffff;
    res = bsort32(res, lane);
    int nchunks = (cnt + 31) >> 5;
    for (int c = 1; c < nchunks; c++) {
        int idx = c * 32 + lane;
        int v = (idx < cnt) ? buf[idx] : 0x7fffffff;
        v = bsort32(v, lane);
        int vr = __shfl_sync(0xffffffffu, v, 31 - lane);
        res = min(res, vr);
#pragma unroll
        for (int j = 16; j > 0; j >>= 1) {
            int p = __shfl_xor_sync(0xffffffffu, res, j);
            res = ((lane & j) == 0) ? min(res, p) : max(res, p);
        }
    }
    int first = __shfl_sync(0xffffffffu, res, 0);
    int outv = (cnt == 0) ? 0 : ((lane < cnt) ? res : first);
    g_idx[qid * NSAMPLE + lane] = outv;
}

// ---------------------------------------------------------------- K4: grouping (2 queries per 256-thread block)
__global__ void __launch_bounds__(256) group_kernel(
    const float* __restrict__ xyz, const float* __restrict__ new_xyz,
    float* __restrict__ out)
{
    __shared__ int   sidx[2][NSAMPLE];
    __shared__ __align__(16) float T[2][NSAMPLE][OUTC];   // stride 67

    int t    = threadIdx.x;
    int ql   = t >> 7;                 // 0/1: query within block
    int tl   = t & 127;
    int lane = t & 31;
    int w    = tl >> 5;                // warp within query 0..3
    int qid  = blockIdx.x * 2 + ql;
    int b = qid / NPOINT;
    int p = qid % NPOINT;

    if (tl < 32) sidx[ql][tl] = g_idx[qid * NSAMPLE + tl];
    __syncthreads();

    // ---- scattered xyz gather first (long-latency, overlaps feature gather)
    float xv = 0.0f; int cxi = 0, sxi = 0;
    if (tl < 96) {
        cxi = tl >> 5; sxi = tl & 31;
        xv = xyz[((size_t)(b * NN + sidx[ql][sxi])) * 3 + cxi]
           - new_xyz[((size_t)(b * NPOINT + p)) * 3 + cxi];
    }

    // ---- feature gather: warp w loads samples w*8..w*8+7, full row per warp
#pragma unroll
    for (int j = 0; j < 8; j++) {
        int s = w * 8 + j;                 // parity(s) == parity(j)
        int row = sidx[ql][s];
        const float2* rp = (const float2*)(g_ft + ((size_t)(b * NN + row)) * CC);
        float2 v = rp[lane];
        if ((j & 1) == 0) {
            *(float2*)&T[ql][s][2 * lane] = v;
        } else {
            T[ql][s][2 * lane + 0] = v.x;
            T[ql][s][2 * lane + 1] = v.y;
        }
    }
    __syncthreads();

    if (tl < 96)
        out[(((size_t)b * OUTC + cxi) * NPOINT + p) * NSAMPLE + sxi] = xv;

    // ---- feature output: float4 along sample dim, STG.128 coalesced
    float4* out4 = (float4*)(out + (((size_t)b * OUTC + 3) * NPOINT + p) * NSAMPLE);
#pragma unroll
    for (int k = 0; k < 4; k++) {
        int f  = tl + 128 * k;
        int c  = f >> 3;
        int sq = f & 7;
        float4 wv;
        wv.x = T[ql][4 * sq + 0][c];
        wv.y = T[ql][4 * sq + 1][c];
        wv.z = T[ql][4 * sq + 2][c];
        wv.w = T[ql][4 * sq + 3][c];
        out4[(size_t)c * (NPOINT * NSAMPLE / 4) + sq] = wv;
    }
}

// ---------------------------------------------------------------- launch
extern "C" void kernel_launch(void* const* d_in, const int* in_sizes, int n_in,
                              void* d_out, int out_size)
{
    const float* xyz     = (const float*)d_in[0];
    const float* new_xyz = (const float*)d_in[1];
    const float* feat    = (const float*)d_in[2];
    float* out = (float*)d_out;

    hist_kernel<<<HIST_BLOCKS, 256>>>(xyz);
    scan_scatter_kernel<<<SC_BLOCKS, 256>>>(xyz);
    bq_tr_kernel<<<BQ_BLOCKS + TR_TILES, 256>>>(new_xyz, feat);
    group_kernel<<<BB * NPOINT / 2, 256>>>(xyz, new_xyz, out);
}